// round 1
// baseline (speedup 1.0000x reference)
#include <cuda_runtime.h>
#include <math.h>

// ---------------- problem constants ----------------
#define BATCH   4
#define NTOK    1024          // 32*32 tokens per image
#define EMBED   768
#define HEADS   12
#define HD      64
#define DEPTH   4
#define QKVC    2304          // 3*EMBED
#define MLPD    3072
#define MTOT    4096          // BATCH*NTOK
#define BH      48            // BATCH*HEADS
#define RELT    63            // 2*32-1

// ---------------- scratch (static device allocations; no cudaMalloc) -------
__device__ float g_h[MTOT * EMBED];
__device__ float g_ln[MTOT * EMBED];
__device__ float g_qkv[MTOT * QKVC];
__device__ float g_scores[(size_t)BH * NTOK * NTOK];     // 201 MB
__device__ float g_attnout[MTOT * EMBED];
__device__ float g_mlp[MTOT * MLPD];
__device__ float g_relh[BH * NTOK * 32];
__device__ float g_relw[BH * NTOK * 32];
__device__ float g_col[MTOT * EMBED];                    // im2col
__device__ float g_wt[EMBED * EMBED];                    // conv_w transposed

// ---------------- helpers ----------------
__device__ __forceinline__ float gelu_exact(float x) {
    return 0.5f * x * (1.0f + erff(x * 0.70710678118654752440f));
}

// 256-thread block reduce; result broadcast to all threads. `red` = 8 floats.
__device__ __forceinline__ float blockSum256(float v, float* red) {
    const int tid = threadIdx.x;
    #pragma unroll
    for (int o = 16; o > 0; o >>= 1) v += __shfl_xor_sync(0xffffffffu, v, o);
    if ((tid & 31) == 0) red[tid >> 5] = v;
    __syncthreads();
    float t = 0.f;
    #pragma unroll
    for (int i = 0; i < 8; i++) t += red[i];
    return t;
}
__device__ __forceinline__ float blockMax256(float v, float* red) {
    const int tid = threadIdx.x;
    #pragma unroll
    for (int o = 16; o > 0; o >>= 1) v = fmaxf(v, __shfl_xor_sync(0xffffffffu, v, o));
    if ((tid & 31) == 0) red[tid >> 5] = v;
    __syncthreads();
    float t = -INFINITY;
    #pragma unroll
    for (int i = 0; i < 8; i++) t = fmaxf(t, red[i]);
    return t;
}

// ---------------- generic NN SGEMM, 128x128x16 tile, 8x8/thread ------------
// EPI: 1 = +bias, 2 = +bias+res[m*N+n], 3 = gelu(+bias),
//      4 = +bias + res[(m%1024)*N+n]  (pos-embed broadcast over batch)
template <int EPI>
__global__ void __launch_bounds__(256, 2) sgemm_nn(
    int M, int N, int K,
    const float* __restrict__ A, const float* __restrict__ B,
    float* __restrict__ C,
    const float* __restrict__ bias, const float* __restrict__ res)
{
    constexpr int BK = 16;
    __shared__ float As[BK][128];
    __shared__ float Bs[BK][128];

    const int tid = threadIdx.x;
    const int tn = tid & 15, tm = tid >> 4;

    const float* Ab = A + (size_t)blockIdx.y * 128 * K;
    const float* Bb = B + blockIdx.x * 128;

    float acc[8][8];
    #pragma unroll
    for (int i = 0; i < 8; i++)
        #pragma unroll
        for (int j = 0; j < 8; j++) acc[i][j] = 0.f;

    const int aRow = tid >> 2;          // 0..63
    const int aCol = (tid & 3) << 2;    // 0,4,8,12
    const int bRow = tid >> 5;          // 0..7
    const int bCol = (tid & 31) << 2;   // 0..124

    for (int k0 = 0; k0 < K; k0 += BK) {
        #pragma unroll
        for (int r = 0; r < 128; r += 64) {
            float4 v = *reinterpret_cast<const float4*>(
                Ab + (size_t)(aRow + r) * K + k0 + aCol);
            As[aCol + 0][aRow + r] = v.x;
            As[aCol + 1][aRow + r] = v.y;
            As[aCol + 2][aRow + r] = v.z;
            As[aCol + 3][aRow + r] = v.w;
        }
        #pragma unroll
        for (int r = 0; r < BK; r += 8) {
            *reinterpret_cast<float4*>(&Bs[bRow + r][bCol]) =
                *reinterpret_cast<const float4*>(Bb + (size_t)(k0 + bRow + r) * N + bCol);
        }
        __syncthreads();
        #pragma unroll
        for (int kk = 0; kk < BK; kk++) {
            float af[8], bf[8];
            #pragma unroll
            for (int i = 0; i < 8; i++) af[i] = As[kk][tm * 8 + i];
            #pragma unroll
            for (int j = 0; j < 8; j++) bf[j] = Bs[kk][tn * 8 + j];
            #pragma unroll
            for (int i = 0; i < 8; i++)
                #pragma unroll
                for (int j = 0; j < 8; j++) acc[i][j] = fmaf(af[i], bf[j], acc[i][j]);
        }
        __syncthreads();
    }

    const int m0 = blockIdx.y * 128 + tm * 8;
    const int n0 = blockIdx.x * 128 + tn * 8;
    #pragma unroll
    for (int i = 0; i < 8; i++) {
        const int m = m0 + i;
        #pragma unroll
        for (int j = 0; j < 8; j++) {
            const int n = n0 + j;
            float c = acc[i][j];
            if (EPI == 1)      c += bias[n];
            else if (EPI == 2) c += bias[n] + res[(size_t)m * N + n];
            else if (EPI == 3) c = gelu_exact(c + bias[n]);
            else if (EPI == 4) c += bias[n] + res[(size_t)(m & (NTOK - 1)) * N + n];
            C[(size_t)m * N + n] = c;
        }
    }
}

// ---------------- im2col for 16x16/stride16 conv ----------------
__global__ void __launch_bounds__(256) im2col_k(const float* __restrict__ x,
                                                float* __restrict__ col)
{
    int idx = blockIdx.x * 256 + threadIdx.x;       // < 4096*768
    int m = idx / EMBED, k = idx - m * EMBED;
    int b = m >> 10;
    int gy = (m >> 5) & 31, gx = m & 31;
    int ci = k >> 8;
    int ph = (k >> 4) & 15, pw = k & 15;
    col[idx] = x[(((size_t)b * 3 + ci) * 512 + gy * 16 + ph) * 512 + gx * 16 + pw];
}

// transpose conv_w [768 out][768 k] -> wt [768 k][768 out]
__global__ void __launch_bounds__(256) transpose768_k(const float* __restrict__ w,
                                                      float* __restrict__ wt)
{
    int idx = blockIdx.x * 256 + threadIdx.x;       // < 768*768
    int k = idx / EMBED, co = idx - k * EMBED;
    wt[idx] = w[(size_t)co * EMBED + k];
}

// ---------------- LayerNorm (768, one row per block) ----------------
__global__ void __launch_bounds__(256) layernorm_k(
    const float* __restrict__ in, const float* __restrict__ w,
    const float* __restrict__ b, float* __restrict__ out)
{
    __shared__ float red[8];
    const int tid = threadIdx.x;
    const float* p = in + (size_t)blockIdx.x * EMBED;
    float* q = out + (size_t)blockIdx.x * EMBED;
    float x0 = p[tid], x1 = p[tid + 256], x2 = p[tid + 512];
    float s  = blockSum256(x0 + x1 + x2, red);
    __syncthreads();
    float sq = blockSum256(x0 * x0 + x1 * x1 + x2 * x2, red);
    float mean = s * (1.f / 768.f);
    float var = sq * (1.f / 768.f) - mean * mean;
    float rs = rsqrtf(var + 1e-5f);
    q[tid]       = (x0 - mean) * rs * w[tid]       + b[tid];
    q[tid + 256] = (x1 - mean) * rs * w[tid + 256] + b[tid + 256];
    q[tid + 512] = (x2 - mean) * rs * w[tid + 512] + b[tid + 512];
}

// ---------------- rel-pos bias tables ----------------
// relh[bh][q][kh] = sum_d q[bh,q,d] * rel_pos_h[hq-kh+31][d]; likewise relw.
__global__ void __launch_bounds__(64) rel_tables_k(
    const float* __restrict__ qkv, const float* __restrict__ rph,
    const float* __restrict__ rpw, float* __restrict__ relh,
    float* __restrict__ relw)
{
    __shared__ float qv[HD];
    const int bq = blockIdx.x;
    const int bh = bq >> 10, q = bq & 1023;
    const int b = bh / HEADS, head = bh % HEADS;
    const int hq = q >> 5, wq = q & 31;
    const int tid = threadIdx.x;
    qv[tid] = qkv[((size_t)(b * NTOK + q)) * QKVC + head * HD + tid];
    __syncthreads();
    const int kidx = tid & 31;
    const float* r;
    float* out;
    if (tid < 32) { r = rph + (hq - kidx + 31) * HD; out = relh; }
    else          { r = rpw + (wq - kidx + 31) * HD; out = relw; }
    float s = 0.f;
    #pragma unroll
    for (int d = 0; d < HD; d++) s = fmaf(qv[d], r[d], s);
    out[((size_t)bh * NTOK + q) * 32 + kidx] = s;
}

// ---------------- attention scores: q·kT * scale + rel bias ----------------
__global__ void __launch_bounds__(256) attn_scores_k(
    const float* __restrict__ qkv, const float* __restrict__ relh,
    const float* __restrict__ relw, float* __restrict__ scores)
{
    __shared__ float Qs[64][65];
    __shared__ float Ks[64][65];
    const int bh = blockIdx.z;
    const int b = bh / HEADS, head = bh % HEADS;
    const float* qb = qkv + (size_t)b * NTOK * QKVC + head * HD;
    const float* kb = qb + EMBED;
    const int tid = threadIdx.x;
    const int m0 = blockIdx.y * 64, n0 = blockIdx.x * 64;
    const int lr = tid >> 4;          // 0..15
    const int lc = (tid & 15) << 2;   // 0..60
    #pragma unroll
    for (int r = 0; r < 64; r += 16) {
        float4 v = *reinterpret_cast<const float4*>(qb + (size_t)(m0 + lr + r) * QKVC + lc);
        Qs[lc + 0][lr + r] = v.x; Qs[lc + 1][lr + r] = v.y;
        Qs[lc + 2][lr + r] = v.z; Qs[lc + 3][lr + r] = v.w;
        float4 u = *reinterpret_cast<const float4*>(kb + (size_t)(n0 + lr + r) * QKVC + lc);
        Ks[lc + 0][lr + r] = u.x; Ks[lc + 1][lr + r] = u.y;
        Ks[lc + 2][lr + r] = u.z; Ks[lc + 3][lr + r] = u.w;
    }
    __syncthreads();
    const int tm = tid >> 4, tn = tid & 15;
    float acc[4][4] = {};
    #pragma unroll
    for (int kk = 0; kk < 64; kk++) {
        float a[4], c[4];
        #pragma unroll
        for (int i = 0; i < 4; i++) a[i] = Qs[kk][tm * 4 + i];
        #pragma unroll
        for (int j = 0; j < 4; j++) c[j] = Ks[kk][tn * 4 + j];
        #pragma unroll
        for (int i = 0; i < 4; i++)
            #pragma unroll
            for (int j = 0; j < 4; j++) acc[i][j] = fmaf(a[i], c[j], acc[i][j]);
    }
    const size_t rbase = (size_t)bh * NTOK;
    #pragma unroll
    for (int i = 0; i < 4; i++) {
        const int qi = m0 + tm * 4 + i;
        const float* rh = relh + (rbase + qi) * 32;
        const float* rw = relw + (rbase + qi) * 32;
        float* srow = scores + (rbase + qi) * NTOK;
        #pragma unroll
        for (int j = 0; j < 4; j++) {
            const int kj = n0 + tn * 4 + j;
            srow[kj] = acc[i][j] * 0.125f + rh[kj >> 5] + rw[kj & 31];
        }
    }
}

// ---------------- softmax over 1024 cols, one row per block ----------------
__global__ void __launch_bounds__(256) softmax1024_k(float* __restrict__ scores)
{
    __shared__ float red[8];
    float* p = scores + (size_t)blockIdx.x * NTOK;
    const int tid = threadIdx.x;
    float4 v = reinterpret_cast<float4*>(p)[tid];
    float m = blockMax256(fmaxf(fmaxf(v.x, v.y), fmaxf(v.z, v.w)), red);
    v.x = expf(v.x - m); v.y = expf(v.y - m);
    v.z = expf(v.z - m); v.w = expf(v.w - m);
    __syncthreads();
    float s = blockSum256(v.x + v.y + v.z + v.w, red);
    float inv = 1.f / s;
    v.x *= inv; v.y *= inv; v.z *= inv; v.w *= inv;
    reinterpret_cast<float4*>(p)[tid] = v;
}

// ---------------- attn @ V, writes head-interleaved [4096][768] ------------
__global__ void __launch_bounds__(256) attn_av_k(
    const float* __restrict__ scores, const float* __restrict__ qkv,
    float* __restrict__ outbuf)
{
    __shared__ float As[32][65];
    __shared__ float Bs[32][64];
    const int bh = blockIdx.z;
    const int b = bh / HEADS, head = bh % HEADS;
    const int m0 = blockIdx.y * 64;
    const float* Ab = scores + ((size_t)bh * NTOK + m0) * NTOK;
    const float* Vb = qkv + (size_t)b * NTOK * QKVC + 2 * EMBED + head * HD;
    const int tid = threadIdx.x;
    const int ar = tid >> 3;          // 0..31 (m)
    const int ac = (tid & 7) << 2;    // 0..28 (kk)
    const int br = tid >> 4;          // 0..15 (kk)
    const int bc = (tid & 15) << 2;   // 0..60 (d)
    const int tm = tid >> 4, tn = tid & 15;
    float acc[4][4] = {};
    for (int k0 = 0; k0 < NTOK; k0 += 32) {
        #pragma unroll
        for (int r = 0; r < 64; r += 32) {
            float4 v = *reinterpret_cast<const float4*>(
                Ab + (size_t)(ar + r) * NTOK + k0 + ac);
            As[ac + 0][ar + r] = v.x; As[ac + 1][ar + r] = v.y;
            As[ac + 2][ar + r] = v.z; As[ac + 3][ar + r] = v.w;
        }
        #pragma unroll
        for (int r = 0; r < 32; r += 16) {
            *reinterpret_cast<float4*>(&Bs[br + r][bc]) =
                *reinterpret_cast<const float4*>(Vb + (size_t)(k0 + br + r) * QKVC + bc);
        }
        __syncthreads();
        #pragma unroll
        for (int kk = 0; kk < 32; kk++) {
            float a[4], c[4];
            #pragma unroll
            for (int i = 0; i < 4; i++) a[i] = As[kk][tm * 4 + i];
            #pragma unroll
            for (int j = 0; j < 4; j++) c[j] = Bs[kk][tn * 4 + j];
            #pragma unroll
            for (int i = 0; i < 4; i++)
                #pragma unroll
                for (int j = 0; j < 4; j++) acc[i][j] = fmaf(a[i], c[j], acc[i][j]);
        }
        __syncthreads();
    }
    #pragma unroll
    for (int i = 0; i < 4; i++) {
        const int m = m0 + tm * 4 + i;
        float* dst = outbuf + ((size_t)b * NTOK + m) * EMBED + head * HD + tn * 4;
        #pragma unroll
        for (int j = 0; j < 4; j++) dst[j] = acc[i][j];
    }
}

// ---------------- host launcher ----------------
extern "C" void kernel_launch(void* const* d_in, const int* in_sizes, int n_in,
                              void* d_out, int out_size)
{
    const float* x       = (const float*)d_in[0];
    const float* conv_w  = (const float*)d_in[1];
    const float* conv_b  = (const float*)d_in[2];
    const float* pos     = (const float*)d_in[3];
    const float* ln1_w   = (const float*)d_in[4];
    const float* ln1_b   = (const float*)d_in[5];
    const float* qkv_w   = (const float*)d_in[6];
    const float* qkv_b   = (const float*)d_in[7];
    const float* proj_w  = (const float*)d_in[8];
    const float* proj_b  = (const float*)d_in[9];
    const float* rph     = (const float*)d_in[10];
    const float* rpw     = (const float*)d_in[11];
    const float* ln2_w   = (const float*)d_in[12];
    const float* ln2_b   = (const float*)d_in[13];
    const float* fc1_w   = (const float*)d_in[14];
    const float* fc1_b   = (const float*)d_in[15];
    const float* fc2_w   = (const float*)d_in[16];
    const float* fc2_b   = (const float*)d_in[17];
    float* out = (float*)d_out;

    float *h, *ln, *qkv, *scores, *attnout, *mlp, *relh, *relw, *col, *wt;
    cudaGetSymbolAddress((void**)&h, g_h);
    cudaGetSymbolAddress((void**)&ln, g_ln);
    cudaGetSymbolAddress((void**)&qkv, g_qkv);
    cudaGetSymbolAddress((void**)&scores, g_scores);
    cudaGetSymbolAddress((void**)&attnout, g_attnout);
    cudaGetSymbolAddress((void**)&mlp, g_mlp);
    cudaGetSymbolAddress((void**)&relh, g_relh);
    cudaGetSymbolAddress((void**)&relw, g_relw);
    cudaGetSymbolAddress((void**)&col, g_col);
    cudaGetSymbolAddress((void**)&wt, g_wt);

    // ---- patch embed: conv as im2col GEMM, + conv_b + pos_embed -> h ----
    transpose768_k<<<(EMBED * EMBED) / 256, 256>>>(conv_w, wt);
    im2col_k<<<(MTOT * EMBED) / 256, 256>>>(x, col);
    sgemm_nn<4><<<dim3(EMBED / 128, MTOT / 128), 256>>>(
        MTOT, EMBED, EMBED, col, wt, h, conv_b, pos);

    for (int L = 0; L < DEPTH; L++) {
        // LN1
        layernorm_k<<<MTOT, 256>>>(h, ln1_w + L * EMBED, ln1_b + L * EMBED, ln);
        // QKV
        sgemm_nn<1><<<dim3(QKVC / 128, MTOT / 128), 256>>>(
            MTOT, QKVC, EMBED, ln, qkv_w + (size_t)L * EMBED * QKVC, qkv,
            qkv_b + L * QKVC, nullptr);
        // rel-pos tables
        rel_tables_k<<<BH * NTOK, 64>>>(qkv, rph + L * RELT * HD,
                                        rpw + L * RELT * HD, relh, relw);
        // scores = q kT * scale + bias
        attn_scores_k<<<dim3(16, 16, BH), 256>>>(qkv, relh, relw, scores);
        // softmax
        softmax1024_k<<<BH * NTOK, 256>>>(scores);
        // attn @ V -> [4096][768] head-interleaved
        attn_av_k<<<dim3(1, 16, BH), 256>>>(scores, qkv, attnout);
        // proj + residual -> h
        sgemm_nn<2><<<dim3(EMBED / 128, MTOT / 128), 256>>>(
            MTOT, EMBED, EMBED, attnout, proj_w + (size_t)L * EMBED * EMBED, h,
            proj_b + L * EMBED, h);
        // LN2
        layernorm_k<<<MTOT, 256>>>(h, ln2_w + L * EMBED, ln2_b + L * EMBED, ln);
        // fc1 + GELU
        sgemm_nn<3><<<dim3(MLPD / 128, MTOT / 128), 256>>>(
            MTOT, MLPD, EMBED, ln, fc1_w + (size_t)L * EMBED * MLPD, mlp,
            fc1_b + L * MLPD, nullptr);
        // fc2 + residual -> h (or final output)
        float* dst = (L == DEPTH - 1) ? out : h;
        sgemm_nn<2><<<dim3(EMBED / 128, MTOT / 128), 256>>>(
            MTOT, EMBED, MLPD, mlp, fc2_w + (size_t)L * MLPD * EMBED, dst,
            fc2_b + L * EMBED, h);
    }
}

// round 2
// speedup vs baseline: 1.6397x; 1.6397x over previous
#include <cuda_runtime.h>
#include <math.h>
#include <stdint.h>

// ---------------- problem constants ----------------
#define BATCH   4
#define NTOK    1024          // 32*32 tokens per image
#define EMBED   768
#define HEADS   12
#define HD      64
#define DEPTH   4
#define QKVC    2304          // 3*EMBED
#define MLPD    3072
#define MTOT    4096          // BATCH*NTOK
#define BH      48            // BATCH*HEADS
#define RELT    63            // 2*32-1

// ---------------- scratch (static device allocations; no cudaMalloc) -------
__device__ float g_h[MTOT * EMBED];
__device__ float g_ln[MTOT * EMBED];
__device__ float g_qkv[MTOT * QKVC];
__device__ float g_scores[(size_t)BH * NTOK * NTOK];     // 201 MB
__device__ float g_attnout[MTOT * EMBED];
__device__ float g_mlp[MTOT * MLPD];
__device__ float g_relh[BH * NTOK * 32];
__device__ float g_relw[BH * NTOK * 32];
__device__ float g_col[MTOT * EMBED];                    // im2col
__device__ float g_wt[EMBED * EMBED];                    // conv_w transposed

// ---------------- helpers ----------------
__device__ __forceinline__ float gelu_exact(float x) {
    return 0.5f * x * (1.0f + erff(x * 0.70710678118654752440f));
}

__device__ __forceinline__ float blockSum256(float v, float* red) {
    const int tid = threadIdx.x;
    #pragma unroll
    for (int o = 16; o > 0; o >>= 1) v += __shfl_xor_sync(0xffffffffu, v, o);
    if ((tid & 31) == 0) red[tid >> 5] = v;
    __syncthreads();
    float t = 0.f;
    #pragma unroll
    for (int i = 0; i < 8; i++) t += red[i];
    return t;
}
__device__ __forceinline__ float blockMax256(float v, float* red) {
    const int tid = threadIdx.x;
    #pragma unroll
    for (int o = 16; o > 0; o >>= 1) v = fmaxf(v, __shfl_xor_sync(0xffffffffu, v, o));
    if ((tid & 31) == 0) red[tid >> 5] = v;
    __syncthreads();
    float t = -INFINITY;
    #pragma unroll
    for (int i = 0; i < 8; i++) t = fmaxf(t, red[i]);
    return t;
}

// RNA-round a float toward tf32 (add half of dropped-bit range; HW truncates)
__device__ __forceinline__ float rna_tf32(float x) {
    return __uint_as_float(__float_as_uint(x) + 0x1000u);
}
__device__ __forceinline__ float4 rna4(float4 v) {
    v.x = rna_tf32(v.x); v.y = rna_tf32(v.y);
    v.z = rna_tf32(v.z); v.w = rna_tf32(v.w);
    return v;
}

__device__ __forceinline__ void mma_tf32(float* d, const uint32_t* a,
                                         const uint32_t* b) {
    asm volatile(
        "mma.sync.aligned.m16n8k8.row.col.f32.tf32.tf32.f32 "
        "{%0,%1,%2,%3}, {%4,%5,%6,%7}, {%8,%9}, {%0,%1,%2,%3};\n"
        : "+f"(d[0]), "+f"(d[1]), "+f"(d[2]), "+f"(d[3])
        : "r"(a[0]), "r"(a[1]), "r"(a[2]), "r"(a[3]), "r"(b[0]), "r"(b[1]));
}

// ---------------- tf32 tensor-core GEMM, 128x128x16 tile, 8 warps ----------
// EPI: 1 = +bias, 2 = +bias+res[m*N+n], 3 = gelu(+bias),
//      4 = +bias + res[(m%1024)*N+n]
template <int EPI>
__global__ void __launch_bounds__(256) mma_gemm(
    int M, int N, int K,
    const float* __restrict__ A, const float* __restrict__ B,
    float* __restrict__ C,
    const float* __restrict__ bias, const float* __restrict__ res)
{
    constexpr int BM = 128, BN = 128, BK = 16;
    __shared__ float As[2][BM][BK + 4];   // [m][k] stride 20 -> conflict-free frags
    __shared__ float Bs[2][BK][BN + 8];   // [k][n] stride 136 -> conflict-free frags

    const int tid = threadIdx.x;
    const int lane = tid & 31;
    const int wid = tid >> 5;
    const int wm = wid & 1;              // 0..1  (64 rows each)
    const int wn = wid >> 1;             // 0..3  (32 cols each)
    const int g = lane >> 2, tg = lane & 3;

    const float* Ab = A + (size_t)blockIdx.y * BM * K;
    const float* Bb = B + blockIdx.x * BN;

    float acc[4][4][4];
    #pragma unroll
    for (int i = 0; i < 4; i++)
        #pragma unroll
        for (int j = 0; j < 4; j++)
            #pragma unroll
            for (int r = 0; r < 4; r++) acc[i][j][r] = 0.f;

    // staging: A tile 128x16 = 512 f4, B tile 16x128 = 512 f4, 2 f4/thread each
    const int aRow0 = tid >> 2;          // + p*64
    const int aC4   = tid & 3;           // *4 -> k offset
    const int bRow0 = tid >> 5;          // + p*8
    const int bC4   = tid & 31;          // *4 -> n offset

    float4 ra[2], rb[2];
    const int nIter = K / BK;

    // prologue: tile 0
    #pragma unroll
    for (int p = 0; p < 2; p++) {
        ra[p] = *reinterpret_cast<const float4*>(
            Ab + (size_t)(aRow0 + p * 64) * K + aC4 * 4);
        rb[p] = *reinterpret_cast<const float4*>(
            Bb + (size_t)(bRow0 + p * 8) * N + bC4 * 4);
    }
    #pragma unroll
    for (int p = 0; p < 2; p++) {
        *reinterpret_cast<float4*>(&As[0][aRow0 + p * 64][aC4 * 4]) = rna4(ra[p]);
        *reinterpret_cast<float4*>(&Bs[0][bRow0 + p * 8][bC4 * 4]) = rna4(rb[p]);
    }
    __syncthreads();

    int buf = 0;
    for (int it = 0; it < nIter; ++it) {
        if (it + 1 < nIter) {
            const int k0 = (it + 1) * BK;
            #pragma unroll
            for (int p = 0; p < 2; p++) {
                ra[p] = *reinterpret_cast<const float4*>(
                    Ab + (size_t)(aRow0 + p * 64) * K + k0 + aC4 * 4);
                rb[p] = *reinterpret_cast<const float4*>(
                    Bb + (size_t)(k0 + bRow0 + p * 8) * N + bC4 * 4);
            }
        }

        #pragma unroll
        for (int kf = 0; kf < 2; kf++) {
            uint32_t af[4][4];
            uint32_t bf[4][2];
            #pragma unroll
            for (int mf = 0; mf < 4; mf++) {
                const int r = wm * 64 + mf * 16;
                af[mf][0] = __float_as_uint(As[buf][r + g][kf * 8 + tg]);
                af[mf][1] = __float_as_uint(As[buf][r + 8 + g][kf * 8 + tg]);
                af[mf][2] = __float_as_uint(As[buf][r + g][kf * 8 + tg + 4]);
                af[mf][3] = __float_as_uint(As[buf][r + 8 + g][kf * 8 + tg + 4]);
            }
            #pragma unroll
            for (int nf = 0; nf < 4; nf++) {
                const int c = wn * 32 + nf * 8;
                bf[nf][0] = __float_as_uint(Bs[buf][kf * 8 + tg][c + g]);
                bf[nf][1] = __float_as_uint(Bs[buf][kf * 8 + tg + 4][c + g]);
            }
            #pragma unroll
            for (int mf = 0; mf < 4; mf++)
                #pragma unroll
                for (int nf = 0; nf < 4; nf++)
                    mma_tf32(acc[mf][nf], af[mf], bf[nf]);
        }

        if (it + 1 < nIter) {
            #pragma unroll
            for (int p = 0; p < 2; p++) {
                *reinterpret_cast<float4*>(&As[buf ^ 1][aRow0 + p * 64][aC4 * 4]) =
                    rna4(ra[p]);
                *reinterpret_cast<float4*>(&Bs[buf ^ 1][bRow0 + p * 8][bC4 * 4]) =
                    rna4(rb[p]);
            }
        }
        __syncthreads();
        buf ^= 1;
    }

    // epilogue
    #pragma unroll
    for (int mf = 0; mf < 4; mf++) {
        const int row0 = blockIdx.y * 128 + wm * 64 + mf * 16 + g;
        #pragma unroll
        for (int nf = 0; nf < 4; nf++) {
            const int col = blockIdx.x * 128 + wn * 32 + nf * 8 + tg * 2;
            #pragma unroll
            for (int half = 0; half < 2; half++) {
                const int m = row0 + half * 8;
                float c0 = acc[mf][nf][half * 2 + 0];
                float c1 = acc[mf][nf][half * 2 + 1];
                if (EPI == 1) {
                    c0 += bias[col]; c1 += bias[col + 1];
                } else if (EPI == 2) {
                    c0 += bias[col]     + res[(size_t)m * N + col];
                    c1 += bias[col + 1] + res[(size_t)m * N + col + 1];
                } else if (EPI == 3) {
                    c0 = gelu_exact(c0 + bias[col]);
                    c1 = gelu_exact(c1 + bias[col + 1]);
                } else if (EPI == 4) {
                    c0 += bias[col]     + res[(size_t)(m & (NTOK - 1)) * N + col];
                    c1 += bias[col + 1] + res[(size_t)(m & (NTOK - 1)) * N + col + 1];
                }
                float2 v = make_float2(c0, c1);
                *reinterpret_cast<float2*>(&C[(size_t)m * N + col]) = v;
            }
        }
    }
}

// ---------------- im2col for 16x16/stride16 conv ----------------
__global__ void __launch_bounds__(256) im2col_k(const float* __restrict__ x,
                                                float* __restrict__ col)
{
    int idx = blockIdx.x * 256 + threadIdx.x;       // < 4096*768
    int m = idx / EMBED, k = idx - m * EMBED;
    int b = m >> 10;
    int gy = (m >> 5) & 31, gx = m & 31;
    int ci = k >> 8;
    int ph = (k >> 4) & 15, pw = k & 15;
    col[idx] = x[(((size_t)b * 3 + ci) * 512 + gy * 16 + ph) * 512 + gx * 16 + pw];
}

// transpose conv_w [768 out][768 k] -> wt [768 k][768 out]
__global__ void __launch_bounds__(256) transpose768_k(const float* __restrict__ w,
                                                      float* __restrict__ wt)
{
    int idx = blockIdx.x * 256 + threadIdx.x;       // < 768*768
    int k = idx / EMBED, co = idx - k * EMBED;
    wt[idx] = w[(size_t)co * EMBED + k];
}

// ---------------- LayerNorm (768, one row per block) ----------------
__global__ void __launch_bounds__(256) layernorm_k(
    const float* __restrict__ in, const float* __restrict__ w,
    const float* __restrict__ b, float* __restrict__ out)
{
    __shared__ float red[8];
    const int tid = threadIdx.x;
    const float* p = in + (size_t)blockIdx.x * EMBED;
    float* q = out + (size_t)blockIdx.x * EMBED;
    float x0 = p[tid], x1 = p[tid + 256], x2 = p[tid + 512];
    float s  = blockSum256(x0 + x1 + x2, red);
    __syncthreads();
    float sq = blockSum256(x0 * x0 + x1 * x1 + x2 * x2, red);
    float mean = s * (1.f / 768.f);
    float var = sq * (1.f / 768.f) - mean * mean;
    float rs = rsqrtf(var + 1e-5f);
    q[tid]       = (x0 - mean) * rs * w[tid]       + b[tid];
    q[tid + 256] = (x1 - mean) * rs * w[tid + 256] + b[tid + 256];
    q[tid + 512] = (x2 - mean) * rs * w[tid + 512] + b[tid + 512];
}

// ---------------- rel-pos bias tables ----------------
__global__ void __launch_bounds__(64) rel_tables_k(
    const float* __restrict__ qkv, const float* __restrict__ rph,
    const float* __restrict__ rpw, float* __restrict__ relh,
    float* __restrict__ relw)
{
    __shared__ float qv[HD];
    const int bq = blockIdx.x;
    const int bh = bq >> 10, q = bq & 1023;
    const int b = bh / HEADS, head = bh % HEADS;
    const int hq = q >> 5, wq = q & 31;
    const int tid = threadIdx.x;
    qv[tid] = qkv[((size_t)(b * NTOK + q)) * QKVC + head * HD + tid];
    __syncthreads();
    const int kidx = tid & 31;
    const float* r;
    float* out;
    if (tid < 32) { r = rph + (hq - kidx + 31) * HD; out = relh; }
    else          { r = rpw + (wq - kidx + 31) * HD; out = relw; }
    float s = 0.f;
    #pragma unroll
    for (int d = 0; d < HD; d++) s = fmaf(qv[d], r[d], s);
    out[((size_t)bh * NTOK + q) * 32 + kidx] = s;
}

// ---------------- attention scores: q·kT * scale + rel bias ----------------
__global__ void __launch_bounds__(256) attn_scores_k(
    const float* __restrict__ qkv, const float* __restrict__ relh,
    const float* __restrict__ relw, float* __restrict__ scores)
{
    __shared__ float Qs[64][65];
    __shared__ float Ks[64][65];
    const int bh = blockIdx.z;
    const int b = bh / HEADS, head = bh % HEADS;
    const float* qb = qkv + (size_t)b * NTOK * QKVC + head * HD;
    const float* kb = qb + EMBED;
    const int tid = threadIdx.x;
    const int m0 = blockIdx.y * 64, n0 = blockIdx.x * 64;
    const int lr = tid >> 4;
    const int lc = (tid & 15) << 2;
    #pragma unroll
    for (int r = 0; r < 64; r += 16) {
        float4 v = *reinterpret_cast<const float4*>(qb + (size_t)(m0 + lr + r) * QKVC + lc);
        Qs[lc + 0][lr + r] = v.x; Qs[lc + 1][lr + r] = v.y;
        Qs[lc + 2][lr + r] = v.z; Qs[lc + 3][lr + r] = v.w;
        float4 u = *reinterpret_cast<const float4*>(kb + (size_t)(n0 + lr + r) * QKVC + lc);
        Ks[lc + 0][lr + r] = u.x; Ks[lc + 1][lr + r] = u.y;
        Ks[lc + 2][lr + r] = u.z; Ks[lc + 3][lr + r] = u.w;
    }
    __syncthreads();
    const int tm = tid >> 4, tn = tid & 15;
    float acc[4][4] = {};
    #pragma unroll
    for (int kk = 0; kk < 64; kk++) {
        float a[4], c[4];
        #pragma unroll
        for (int i = 0; i < 4; i++) a[i] = Qs[kk][tm * 4 + i];
        #pragma unroll
        for (int j = 0; j < 4; j++) c[j] = Ks[kk][tn * 4 + j];
        #pragma unroll
        for (int i = 0; i < 4; i++)
            #pragma unroll
            for (int j = 0; j < 4; j++) acc[i][j] = fmaf(a[i], c[j], acc[i][j]);
    }
    const size_t rbase = (size_t)bh * NTOK;
    #pragma unroll
    for (int i = 0; i < 4; i++) {
        const int qi = m0 + tm * 4 + i;
        const float* rh = relh + (rbase + qi) * 32;
        const float* rw = relw + (rbase + qi) * 32;
        float* srow = scores + (rbase + qi) * NTOK;
        #pragma unroll
        for (int j = 0; j < 4; j++) {
            const int kj = n0 + tn * 4 + j;
            srow[kj] = acc[i][j] * 0.125f + rh[kj >> 5] + rw[kj & 31];
        }
    }
}

// ---------------- softmax over 1024 cols, one row per block ----------------
__global__ void __launch_bounds__(256) softmax1024_k(float* __restrict__ scores)
{
    __shared__ float red[8];
    float* p = scores + (size_t)blockIdx.x * NTOK;
    const int tid = threadIdx.x;
    float4 v = reinterpret_cast<float4*>(p)[tid];
    float m = blockMax256(fmaxf(fmaxf(v.x, v.y), fmaxf(v.z, v.w)), red);
    v.x = expf(v.x - m); v.y = expf(v.y - m);
    v.z = expf(v.z - m); v.w = expf(v.w - m);
    __syncthreads();
    float s = blockSum256(v.x + v.y + v.z + v.w, red);
    float inv = 1.f / s;
    v.x *= inv; v.y *= inv; v.z *= inv; v.w *= inv;
    reinterpret_cast<float4*>(p)[tid] = v;
}

// ---------------- attn @ V, writes head-interleaved [4096][768] ------------
__global__ void __launch_bounds__(256) attn_av_k(
    const float* __restrict__ scores, const float* __restrict__ qkv,
    float* __restrict__ outbuf)
{
    __shared__ float As[32][65];
    __shared__ float Bs[32][64];
    const int bh = blockIdx.z;
    const int b = bh / HEADS, head = bh % HEADS;
    const int m0 = blockIdx.y * 64;
    const float* Ab = scores + ((size_t)bh * NTOK + m0) * NTOK;
    const float* Vb = qkv + (size_t)b * NTOK * QKVC + 2 * EMBED + head * HD;
    const int tid = threadIdx.x;
    const int ar = tid >> 3;
    const int ac = (tid & 7) << 2;
    const int br = tid >> 4;
    const int bc = (tid & 15) << 2;
    const int tm = tid >> 4, tn = tid & 15;
    float acc[4][4] = {};
    for (int k0 = 0; k0 < NTOK; k0 += 32) {
        #pragma unroll
        for (int r = 0; r < 64; r += 32) {
            float4 v = *reinterpret_cast<const float4*>(
                Ab + (size_t)(ar + r) * NTOK + k0 + ac);
            As[ac + 0][ar + r] = v.x; As[ac + 1][ar + r] = v.y;
            As[ac + 2][ar + r] = v.z; As[ac + 3][ar + r] = v.w;
        }
        #pragma unroll
        for (int r = 0; r < 32; r += 16) {
            *reinterpret_cast<float4*>(&Bs[br + r][bc]) =
                *reinterpret_cast<const float4*>(Vb + (size_t)(k0 + br + r) * QKVC + bc);
        }
        __syncthreads();
        #pragma unroll
        for (int kk = 0; kk < 32; kk++) {
            float a[4], c[4];
            #pragma unroll
            for (int i = 0; i < 4; i++) a[i] = As[kk][tm * 4 + i];
            #pragma unroll
            for (int j = 0; j < 4; j++) c[j] = Bs[kk][tn * 4 + j];
            #pragma unroll
            for (int i = 0; i < 4; i++)
                #pragma unroll
                for (int j = 0; j < 4; j++) acc[i][j] = fmaf(a[i], c[j], acc[i][j]);
        }
        __syncthreads();
    }
    #pragma unroll
    for (int i = 0; i < 4; i++) {
        const int m = m0 + tm * 4 + i;
        float* dst = outbuf + ((size_t)b * NTOK + m) * EMBED + head * HD + tn * 4;
        #pragma unroll
        for (int j = 0; j < 4; j++) dst[j] = acc[i][j];
    }
}

// ---------------- host launcher ----------------
extern "C" void kernel_launch(void* const* d_in, const int* in_sizes, int n_in,
                              void* d_out, int out_size)
{
    const float* x       = (const float*)d_in[0];
    const float* conv_w  = (const float*)d_in[1];
    const float* conv_b  = (const float*)d_in[2];
    const float* pos     = (const float*)d_in[3];
    const float* ln1_w   = (const float*)d_in[4];
    const float* ln1_b   = (const float*)d_in[5];
    const float* qkv_w   = (const float*)d_in[6];
    const float* qkv_b   = (const float*)d_in[7];
    const float* proj_w  = (const float*)d_in[8];
    const float* proj_b  = (const float*)d_in[9];
    const float* rph     = (const float*)d_in[10];
    const float* rpw     = (const float*)d_in[11];
    const float* ln2_w   = (const float*)d_in[12];
    const float* ln2_b   = (const float*)d_in[13];
    const float* fc1_w   = (const float*)d_in[14];
    const float* fc1_b   = (const float*)d_in[15];
    const float* fc2_w   = (const float*)d_in[16];
    const float* fc2_b   = (const float*)d_in[17];
    float* out = (float*)d_out;

    float *h, *ln, *qkv, *scores, *attnout, *mlp, *relh, *relw, *col, *wt;
    cudaGetSymbolAddress((void**)&h, g_h);
    cudaGetSymbolAddress((void**)&ln, g_ln);
    cudaGetSymbolAddress((void**)&qkv, g_qkv);
    cudaGetSymbolAddress((void**)&scores, g_scores);
    cudaGetSymbolAddress((void**)&attnout, g_attnout);
    cudaGetSymbolAddress((void**)&mlp, g_mlp);
    cudaGetSymbolAddress((void**)&relh, g_relh);
    cudaGetSymbolAddress((void**)&relw, g_relw);
    cudaGetSymbolAddress((void**)&col, g_col);
    cudaGetSymbolAddress((void**)&wt, g_wt);

    // ---- patch embed: conv as im2col GEMM, + conv_b + pos_embed -> h ----
    transpose768_k<<<(EMBED * EMBED) / 256, 256>>>(conv_w, wt);
    im2col_k<<<(MTOT * EMBED) / 256, 256>>>(x, col);
    mma_gemm<4><<<dim3(EMBED / 128, MTOT / 128), 256>>>(
        MTOT, EMBED, EMBED, col, wt, h, conv_b, pos);

    for (int L = 0; L < DEPTH; L++) {
        layernorm_k<<<MTOT, 256>>>(h, ln1_w + L * EMBED, ln1_b + L * EMBED, ln);
        mma_gemm<1><<<dim3(QKVC / 128, MTOT / 128), 256>>>(
            MTOT, QKVC, EMBED, ln, qkv_w + (size_t)L * EMBED * QKVC, qkv,
            qkv_b + L * QKVC, nullptr);
        rel_tables_k<<<BH * NTOK, 64>>>(qkv, rph + L * RELT * HD,
                                        rpw + L * RELT * HD, relh, relw);
        attn_scores_k<<<dim3(16, 16, BH), 256>>>(qkv, relh, relw, scores);
        softmax1024_k<<<BH * NTOK, 256>>>(scores);
        attn_av_k<<<dim3(1, 16, BH), 256>>>(scores, qkv, attnout);
        mma_gemm<2><<<dim3(EMBED / 128, MTOT / 128), 256>>>(
            MTOT, EMBED, EMBED, attnout, proj_w + (size_t)L * EMBED * EMBED, h,
            proj_b + L * EMBED, h);
        layernorm_k<<<MTOT, 256>>>(h, ln2_w + L * EMBED, ln2_b + L * EMBED, ln);
        mma_gemm<3><<<dim3(MLPD / 128, MTOT / 128), 256>>>(
            MTOT, MLPD, EMBED, ln, fc1_w + (size_t)L * EMBED * MLPD, mlp,
            fc1_b + L * MLPD, nullptr);
        float* dst = (L == DEPTH - 1) ? out : h;
        mma_gemm<2><<<dim3(EMBED / 128, MTOT / 128), 256>>>(
            MTOT, EMBED, MLPD, mlp, fc2_w + (size_t)L * MLPD * EMBED, dst,
            fc2_b + L * EMBED, h);
    }
}

// round 3
// speedup vs baseline: 2.0305x; 1.2383x over previous
#include <cuda_runtime.h>
#include <math.h>
#include <stdint.h>

// ---------------- problem constants ----------------
#define BATCH   4
#define NTOK    1024
#define EMBED   768
#define HEADS   12
#define HD      64
#define DEPTH   4
#define QKVC    2304
#define MLPD    3072
#define MTOT    4096
#define BH      48
#define RELT    63

// ---------------- scratch ----------------
__device__ float g_h[MTOT * EMBED];
__device__ float g_ln[MTOT * EMBED];
__device__ float g_qkv[MTOT * QKVC];
__device__ float g_attnout[MTOT * EMBED];
__device__ float g_mlp[MTOT * MLPD];
__device__ float g_relh[BH * NTOK * 32];
__device__ float g_relw[BH * NTOK * 32];
__device__ float g_col[MTOT * EMBED];
__device__ float g_wt[EMBED * EMBED];

// ---------------- helpers ----------------
__device__ __forceinline__ float gelu_exact(float x) {
    return 0.5f * x * (1.0f + erff(x * 0.70710678118654752440f));
}
__device__ __forceinline__ float blockSum256(float v, float* red) {
    const int tid = threadIdx.x;
    #pragma unroll
    for (int o = 16; o > 0; o >>= 1) v += __shfl_xor_sync(0xffffffffu, v, o);
    if ((tid & 31) == 0) red[tid >> 5] = v;
    __syncthreads();
    float t = 0.f;
    #pragma unroll
    for (int i = 0; i < 8; i++) t += red[i];
    return t;
}
__device__ __forceinline__ float rna_tf32(float x) {
    return __uint_as_float(__float_as_uint(x) + 0x1000u);
}
__device__ __forceinline__ float4 rna4(float4 v) {
    v.x = rna_tf32(v.x); v.y = rna_tf32(v.y);
    v.z = rna_tf32(v.z); v.w = rna_tf32(v.w);
    return v;
}
__device__ __forceinline__ void mma_tf32(float* d, const uint32_t* a,
                                         const uint32_t* b) {
    asm volatile(
        "mma.sync.aligned.m16n8k8.row.col.f32.tf32.tf32.f32 "
        "{%0,%1,%2,%3}, {%4,%5,%6,%7}, {%8,%9}, {%0,%1,%2,%3};\n"
        : "+f"(d[0]), "+f"(d[1]), "+f"(d[2]), "+f"(d[3])
        : "r"(a[0]), "r"(a[1]), "r"(a[2]), "r"(a[3]), "r"(b[0]), "r"(b[1]));
}

// ---------------- tf32 tensor-core GEMM, 128x128x16 tile, 8 warps ----------
template <int EPI>
__global__ void __launch_bounds__(256) mma_gemm(
    int M, int N, int K,
    const float* __restrict__ A, const float* __restrict__ B,
    float* __restrict__ C,
    const float* __restrict__ bias, const float* __restrict__ res)
{
    constexpr int BM = 128, BN = 128, BK = 16;
    __shared__ float As[2][BM][BK + 4];
    __shared__ float Bs[2][BK][BN + 8];

    const int tid = threadIdx.x;
    const int lane = tid & 31;
    const int wid = tid >> 5;
    const int wm = wid & 1;
    const int wn = wid >> 1;
    const int g = lane >> 2, tg = lane & 3;

    const float* Ab = A + (size_t)blockIdx.y * BM * K;
    const float* Bb = B + blockIdx.x * BN;

    float acc[4][4][4];
    #pragma unroll
    for (int i = 0; i < 4; i++)
        #pragma unroll
        for (int j = 0; j < 4; j++)
            #pragma unroll
            for (int r = 0; r < 4; r++) acc[i][j][r] = 0.f;

    const int aRow0 = tid >> 2;
    const int aC4   = tid & 3;
    const int bRow0 = tid >> 5;
    const int bC4   = tid & 31;

    float4 ra[2], rb[2];
    const int nIter = K / BK;

    #pragma unroll
    for (int p = 0; p < 2; p++) {
        ra[p] = *reinterpret_cast<const float4*>(
            Ab + (size_t)(aRow0 + p * 64) * K + aC4 * 4);
        rb[p] = *reinterpret_cast<const float4*>(
            Bb + (size_t)(bRow0 + p * 8) * N + bC4 * 4);
    }
    #pragma unroll
    for (int p = 0; p < 2; p++) {
        *reinterpret_cast<float4*>(&As[0][aRow0 + p * 64][aC4 * 4]) = rna4(ra[p]);
        *reinterpret_cast<float4*>(&Bs[0][bRow0 + p * 8][bC4 * 4]) = rna4(rb[p]);
    }
    __syncthreads();

    int buf = 0;
    for (int it = 0; it < nIter; ++it) {
        if (it + 1 < nIter) {
            const int k0 = (it + 1) * BK;
            #pragma unroll
            for (int p = 0; p < 2; p++) {
                ra[p] = *reinterpret_cast<const float4*>(
                    Ab + (size_t)(aRow0 + p * 64) * K + k0 + aC4 * 4);
                rb[p] = *reinterpret_cast<const float4*>(
                    Bb + (size_t)(k0 + bRow0 + p * 8) * N + bC4 * 4);
            }
        }
        #pragma unroll
        for (int kf = 0; kf < 2; kf++) {
            uint32_t af[4][4];
            uint32_t bf[4][2];
            #pragma unroll
            for (int mf = 0; mf < 4; mf++) {
                const int r = wm * 64 + mf * 16;
                af[mf][0] = __float_as_uint(As[buf][r + g][kf * 8 + tg]);
                af[mf][1] = __float_as_uint(As[buf][r + 8 + g][kf * 8 + tg]);
                af[mf][2] = __float_as_uint(As[buf][r + g][kf * 8 + tg + 4]);
                af[mf][3] = __float_as_uint(As[buf][r + 8 + g][kf * 8 + tg + 4]);
            }
            #pragma unroll
            for (int nf = 0; nf < 4; nf++) {
                const int c = wn * 32 + nf * 8;
                bf[nf][0] = __float_as_uint(Bs[buf][kf * 8 + tg][c + g]);
                bf[nf][1] = __float_as_uint(Bs[buf][kf * 8 + tg + 4][c + g]);
            }
            #pragma unroll
            for (int mf = 0; mf < 4; mf++)
                #pragma unroll
                for (int nf = 0; nf < 4; nf++)
                    mma_tf32(acc[mf][nf], af[mf], bf[nf]);
        }
        if (it + 1 < nIter) {
            #pragma unroll
            for (int p = 0; p < 2; p++) {
                *reinterpret_cast<float4*>(&As[buf ^ 1][aRow0 + p * 64][aC4 * 4]) =
                    rna4(ra[p]);
                *reinterpret_cast<float4*>(&Bs[buf ^ 1][bRow0 + p * 8][bC4 * 4]) =
                    rna4(rb[p]);
            }
        }
        __syncthreads();
        buf ^= 1;
    }

    #pragma unroll
    for (int mf = 0; mf < 4; mf++) {
        const int row0 = blockIdx.y * 128 + wm * 64 + mf * 16 + g;
        #pragma unroll
        for (int nf = 0; nf < 4; nf++) {
            const int col = blockIdx.x * 128 + wn * 32 + nf * 8 + tg * 2;
            #pragma unroll
            for (int half = 0; half < 2; half++) {
                const int m = row0 + half * 8;
                float c0 = acc[mf][nf][half * 2 + 0];
                float c1 = acc[mf][nf][half * 2 + 1];
                if (EPI == 1) {
                    c0 += bias[col]; c1 += bias[col + 1];
                } else if (EPI == 2) {
                    c0 += bias[col]     + res[(size_t)m * N + col];
                    c1 += bias[col + 1] + res[(size_t)m * N + col + 1];
                } else if (EPI == 3) {
                    c0 = gelu_exact(c0 + bias[col]);
                    c1 = gelu_exact(c1 + bias[col + 1]);
                } else if (EPI == 4) {
                    c0 += bias[col]     + res[(size_t)(m & (NTOK - 1)) * N + col];
                    c1 += bias[col + 1] + res[(size_t)(m & (NTOK - 1)) * N + col + 1];
                }
                *reinterpret_cast<float2*>(&C[(size_t)m * N + col]) =
                    make_float2(c0, c1);
            }
        }
    }
}

// ---------------- im2col ----------------
__global__ void __launch_bounds__(256) im2col_k(const float* __restrict__ x,
                                                float* __restrict__ col)
{
    int idx = blockIdx.x * 256 + threadIdx.x;
    int m = idx / EMBED, k = idx - m * EMBED;
    int b = m >> 10;
    int gy = (m >> 5) & 31, gx = m & 31;
    int ci = k >> 8;
    int ph = (k >> 4) & 15, pw = k & 15;
    col[idx] = x[(((size_t)b * 3 + ci) * 512 + gy * 16 + ph) * 512 + gx * 16 + pw];
}

__global__ void __launch_bounds__(256) transpose768_k(const float* __restrict__ w,
                                                      float* __restrict__ wt)
{
    int idx = blockIdx.x * 256 + threadIdx.x;
    int k = idx / EMBED, co = idx - k * EMBED;
    wt[idx] = w[(size_t)co * EMBED + k];
}

// ---------------- LayerNorm ----------------
__global__ void __launch_bounds__(256) layernorm_k(
    const float* __restrict__ in, const float* __restrict__ w,
    const float* __restrict__ b, float* __restrict__ out)
{
    __shared__ float red[8];
    const int tid = threadIdx.x;
    const float* p = in + (size_t)blockIdx.x * EMBED;
    float* q = out + (size_t)blockIdx.x * EMBED;
    float x0 = p[tid], x1 = p[tid + 256], x2 = p[tid + 512];
    float s  = blockSum256(x0 + x1 + x2, red);
    __syncthreads();
    float sq = blockSum256(x0 * x0 + x1 * x1 + x2 * x2, red);
    float mean = s * (1.f / 768.f);
    float var = sq * (1.f / 768.f) - mean * mean;
    float rs = rsqrtf(var + 1e-5f);
    q[tid]       = (x0 - mean) * rs * w[tid]       + b[tid];
    q[tid + 256] = (x1 - mean) * rs * w[tid + 256] + b[tid + 256];
    q[tid + 512] = (x2 - mean) * rs * w[tid + 512] + b[tid + 512];
}

// ---------------- rel-pos bias tables ----------------
__global__ void __launch_bounds__(64) rel_tables_k(
    const float* __restrict__ qkv, const float* __restrict__ rph,
    const float* __restrict__ rpw, float* __restrict__ relh,
    float* __restrict__ relw)
{
    __shared__ float qv[HD];
    const int bq = blockIdx.x;
    const int bh = bq >> 10, q = bq & 1023;
    const int b = bh / HEADS, head = bh % HEADS;
    const int hq = q >> 5, wq = q & 31;
    const int tid = threadIdx.x;
    qv[tid] = qkv[((size_t)(b * NTOK + q)) * QKVC + head * HD + tid];
    __syncthreads();
    const int kidx = tid & 31;
    const float* r;
    float* out;
    if (tid < 32) { r = rph + (hq - kidx + 31) * HD; out = relh; }
    else          { r = rpw + (wq - kidx + 31) * HD; out = relw; }
    float s = 0.f;
    #pragma unroll
    for (int d = 0; d < HD; d++) s = fmaf(qv[d], r[d], s);
    out[((size_t)bh * NTOK + q) * 32 + kidx] = s;
}

// ---------------- fused flash attention (tf32 MMA) ----------------
struct FlashSmem {
    float K[64][68];    // [key][d], stride 68 -> conflict-free B frags
    float V[64][72];    // [key][d], stride 72 -> conflict-free B frags
    float S[64][68];    // scores / P tile; also Q staging at start
    float rh[64][32];
    float rw[64][32];
    float mrow[64];
    float lrow[64];
    float arow[64];
};

__global__ void __launch_bounds__(256) flash_attn_k(
    const float* __restrict__ qkv, const float* __restrict__ relh,
    const float* __restrict__ relw, float* __restrict__ outbuf)
{
    extern __shared__ char smraw[];
    FlashSmem& sm = *reinterpret_cast<FlashSmem*>(smraw);
    const int qt = blockIdx.x, bh = blockIdx.y;
    const int b = bh / HEADS, head = bh % HEADS;
    const float* Qg = qkv + (size_t)b * NTOK * QKVC + head * HD;
    const float* Kg = Qg + EMBED;
    const float* Vg = Qg + 2 * EMBED;
    const int tid = threadIdx.x, lane = tid & 31, wid = tid >> 5;
    const int wm = wid & 3, wn = wid >> 2;
    const int g = lane >> 2, tg = lane & 3;

    // rel bias tables for this q-tile
    for (int i = tid; i < 64 * 32; i += 256) {
        int r = i >> 5, c = i & 31;
        sm.rh[r][c] = relh[((size_t)bh * NTOK + qt * 64 + r) * 32 + c];
        sm.rw[r][c] = relw[((size_t)bh * NTOK + qt * 64 + r) * 32 + c];
    }
    if (tid < 64) { sm.mrow[tid] = -INFINITY; sm.lrow[tid] = 0.f; }

    // stage Q (rna) into S buffer, then lift to registers
    const int sKey = tid >> 4;           // 0..15
    const int sD4  = (tid & 15) * 4;     // 0..60
    #pragma unroll
    for (int r = 0; r < 4; r++) {
        float4 v = *reinterpret_cast<const float4*>(
            Qg + (size_t)(qt * 64 + sKey + 16 * r) * QKVC + sD4);
        *reinterpret_cast<float4*>(&sm.S[sKey + 16 * r][sD4]) = rna4(v);
    }
    __syncthreads();
    uint32_t aq[8][4];
    #pragma unroll
    for (int kf = 0; kf < 8; kf++) {
        aq[kf][0] = __float_as_uint(sm.S[wm * 16 + g][kf * 8 + tg]);
        aq[kf][1] = __float_as_uint(sm.S[wm * 16 + 8 + g][kf * 8 + tg]);
        aq[kf][2] = __float_as_uint(sm.S[wm * 16 + g][kf * 8 + tg + 4]);
        aq[kf][3] = __float_as_uint(sm.S[wm * 16 + 8 + g][kf * 8 + tg + 4]);
    }

    float oacc[4][4];
    #pragma unroll
    for (int i = 0; i < 4; i++)
        #pragma unroll
        for (int j = 0; j < 4; j++) oacc[i][j] = 0.f;

    // prefetch tile 0
    float4 pk[4], pv[4];
    #pragma unroll
    for (int r = 0; r < 4; r++) {
        pk[r] = *reinterpret_cast<const float4*>(
            Kg + (size_t)(sKey + 16 * r) * QKVC + sD4);
        pv[r] = *reinterpret_cast<const float4*>(
            Vg + (size_t)(sKey + 16 * r) * QKVC + sD4);
    }

    for (int t = 0; t < 16; t++) {
        __syncthreads();   // previous iteration done reading K/V/S
        #pragma unroll
        for (int r = 0; r < 4; r++) {
            *reinterpret_cast<float4*>(&sm.K[sKey + 16 * r][sD4]) = rna4(pk[r]);
            *reinterpret_cast<float4*>(&sm.V[sKey + 16 * r][sD4]) = rna4(pv[r]);
        }
        __syncthreads();
        if (t + 1 < 16) {
            #pragma unroll
            for (int r = 0; r < 4; r++) {
                pk[r] = *reinterpret_cast<const float4*>(
                    Kg + (size_t)((t + 1) * 64 + sKey + 16 * r) * QKVC + sD4);
                pv[r] = *reinterpret_cast<const float4*>(
                    Vg + (size_t)((t + 1) * 64 + sKey + 16 * r) * QKVC + sD4);
            }
        }
        // ---- S = Q K^T ----
        float sacc[4][4];
        #pragma unroll
        for (int i = 0; i < 4; i++)
            #pragma unroll
            for (int j = 0; j < 4; j++) sacc[i][j] = 0.f;
        #pragma unroll
        for (int kf = 0; kf < 8; kf++) {
            uint32_t bf[4][2];
            #pragma unroll
            for (int nf = 0; nf < 4; nf++) {
                const int c = wn * 32 + nf * 8;
                bf[nf][0] = __float_as_uint(sm.K[c + g][kf * 8 + tg]);
                bf[nf][1] = __float_as_uint(sm.K[c + g][kf * 8 + tg + 4]);
            }
            #pragma unroll
            for (int nf = 0; nf < 4; nf++) mma_tf32(sacc[nf], aq[kf], bf[nf]);
        }
        #pragma unroll
        for (int nf = 0; nf < 4; nf++) {
            const int c = wn * 32 + nf * 8 + tg * 2;
            sm.S[wm * 16 + g][c]         = sacc[nf][0] * 0.125f;
            sm.S[wm * 16 + g][c + 1]     = sacc[nf][1] * 0.125f;
            sm.S[wm * 16 + 8 + g][c]     = sacc[nf][2] * 0.125f;
            sm.S[wm * 16 + 8 + g][c + 1] = sacc[nf][3] * 0.125f;
        }
        __syncthreads();
        // ---- online softmax (4 threads per row, 16 cols each) ----
        {
            const int row = tid >> 2, part = tid & 3;
            const float mo = sm.mrow[row];
            const float rhv = sm.rh[row][(t << 1) + (part >> 1)];
            float vals[16];
            float tmax = -INFINITY;
            #pragma unroll
            for (int j = 0; j < 16; j++) {
                float s = sm.S[row][part * 16 + j] + rhv
                        + sm.rw[row][(part & 1) * 16 + j];
                vals[j] = s;
                tmax = fmaxf(tmax, s);
            }
            tmax = fmaxf(tmax, __shfl_xor_sync(0xffffffffu, tmax, 1));
            tmax = fmaxf(tmax, __shfl_xor_sync(0xffffffffu, tmax, 2));
            const float nm = fmaxf(mo, tmax);
            float lsum = 0.f;
            #pragma unroll
            for (int j = 0; j < 16; j++) {
                float p = expf(vals[j] - nm);
                lsum += p;
                sm.S[row][part * 16 + j] = rna_tf32(p);
            }
            lsum += __shfl_xor_sync(0xffffffffu, lsum, 1);
            lsum += __shfl_xor_sync(0xffffffffu, lsum, 2);
            if (part == 0) {
                const float alpha = expf(mo - nm);
                sm.mrow[row] = nm;
                sm.lrow[row] = sm.lrow[row] * alpha + lsum;
                sm.arow[row] = alpha;
            }
        }
        __syncthreads();
        // ---- rescale O, accumulate O += P V ----
        const float a0 = sm.arow[wm * 16 + g];
        const float a1 = sm.arow[wm * 16 + 8 + g];
        #pragma unroll
        for (int nf = 0; nf < 4; nf++) {
            oacc[nf][0] *= a0; oacc[nf][1] *= a0;
            oacc[nf][2] *= a1; oacc[nf][3] *= a1;
        }
        #pragma unroll
        for (int kf = 0; kf < 8; kf++) {
            uint32_t ap[4];
            ap[0] = __float_as_uint(sm.S[wm * 16 + g][kf * 8 + tg]);
            ap[1] = __float_as_uint(sm.S[wm * 16 + 8 + g][kf * 8 + tg]);
            ap[2] = __float_as_uint(sm.S[wm * 16 + g][kf * 8 + tg + 4]);
            ap[3] = __float_as_uint(sm.S[wm * 16 + 8 + g][kf * 8 + tg + 4]);
            uint32_t bf[4][2];
            #pragma unroll
            for (int nf = 0; nf < 4; nf++) {
                const int c = wn * 32 + nf * 8;
                bf[nf][0] = __float_as_uint(sm.V[kf * 8 + tg][c + g]);
                bf[nf][1] = __float_as_uint(sm.V[kf * 8 + tg + 4][c + g]);
            }
            #pragma unroll
            for (int nf = 0; nf < 4; nf++) mma_tf32(oacc[nf], ap, bf[nf]);
        }
    }
    __syncthreads();
    const float li0 = 1.f / sm.lrow[wm * 16 + g];
    const float li1 = 1.f / sm.lrow[wm * 16 + 8 + g];
    const int m0 = qt * 64 + wm * 16 + g;
    #pragma unroll
    for (int nf = 0; nf < 4; nf++) {
        const int d = wn * 32 + nf * 8 + tg * 2;
        float* dst0 = outbuf + ((size_t)b * NTOK + m0) * EMBED + head * HD + d;
        float* dst1 = dst0 + 8 * EMBED;
        *reinterpret_cast<float2*>(dst0) =
            make_float2(oacc[nf][0] * li0, oacc[nf][1] * li0);
        *reinterpret_cast<float2*>(dst1) =
            make_float2(oacc[nf][2] * li1, oacc[nf][3] * li1);
    }
}

// ---------------- host launcher ----------------
extern "C" void kernel_launch(void* const* d_in, const int* in_sizes, int n_in,
                              void* d_out, int out_size)
{
    const float* x       = (const float*)d_in[0];
    const float* conv_w  = (const float*)d_in[1];
    const float* conv_b  = (const float*)d_in[2];
    const float* pos     = (const float*)d_in[3];
    const float* ln1_w   = (const float*)d_in[4];
    const float* ln1_b   = (const float*)d_in[5];
    const float* qkv_w   = (const float*)d_in[6];
    const float* qkv_b   = (const float*)d_in[7];
    const float* proj_w  = (const float*)d_in[8];
    const float* proj_b  = (const float*)d_in[9];
    const float* rph     = (const float*)d_in[10];
    const float* rpw     = (const float*)d_in[11];
    const float* ln2_w   = (const float*)d_in[12];
    const float* ln2_b   = (const float*)d_in[13];
    const float* fc1_w   = (const float*)d_in[14];
    const float* fc1_b   = (const float*)d_in[15];
    const float* fc2_w   = (const float*)d_in[16];
    const float* fc2_b   = (const float*)d_in[17];
    float* out = (float*)d_out;

    float *h, *ln, *qkv, *attnout, *mlp, *relh, *relw, *col, *wt;
    cudaGetSymbolAddress((void**)&h, g_h);
    cudaGetSymbolAddress((void**)&ln, g_ln);
    cudaGetSymbolAddress((void**)&qkv, g_qkv);
    cudaGetSymbolAddress((void**)&attnout, g_attnout);
    cudaGetSymbolAddress((void**)&mlp, g_mlp);
    cudaGetSymbolAddress((void**)&relh, g_relh);
    cudaGetSymbolAddress((void**)&relw, g_relw);
    cudaGetSymbolAddress((void**)&col, g_col);
    cudaGetSymbolAddress((void**)&wt, g_wt);

    static bool attr_set = false;
    if (!attr_set) {
        cudaFuncSetAttribute(flash_attn_k,
                             cudaFuncAttributeMaxDynamicSharedMemorySize,
                             (int)sizeof(FlashSmem));
        attr_set = true;
    }

    transpose768_k<<<(EMBED * EMBED) / 256, 256>>>(conv_w, wt);
    im2col_k<<<(MTOT * EMBED) / 256, 256>>>(x, col);
    mma_gemm<4><<<dim3(EMBED / 128, MTOT / 128), 256>>>(
        MTOT, EMBED, EMBED, col, wt, h, conv_b, pos);

    for (int L = 0; L < DEPTH; L++) {
        layernorm_k<<<MTOT, 256>>>(h, ln1_w + L * EMBED, ln1_b + L * EMBED, ln);
        mma_gemm<1><<<dim3(QKVC / 128, MTOT / 128), 256>>>(
            MTOT, QKVC, EMBED, ln, qkv_w + (size_t)L * EMBED * QKVC, qkv,
            qkv_b + L * QKVC, nullptr);
        rel_tables_k<<<BH * NTOK, 64>>>(qkv, rph + L * RELT * HD,
                                        rpw + L * RELT * HD, relh, relw);
        flash_attn_k<<<dim3(16, BH), 256, sizeof(FlashSmem)>>>(
            qkv, relh, relw, attnout);
        mma_gemm<2><<<dim3(EMBED / 128, MTOT / 128), 256>>>(
            MTOT, EMBED, EMBED, attnout, proj_w + (size_t)L * EMBED * EMBED, h,
            proj_b + L * EMBED, h);
        layernorm_k<<<MTOT, 256>>>(h, ln2_w + L * EMBED, ln2_b + L * EMBED, ln);
        mma_gemm<3><<<dim3(MLPD / 128, MTOT / 128), 256>>>(
            MTOT, MLPD, EMBED, ln, fc1_w + (size_t)L * EMBED * MLPD, mlp,
            fc1_b + L * MLPD, nullptr);
        float* dst = (L == DEPTH - 1) ? out : h;
        mma_gemm<2><<<dim3(EMBED / 128, MTOT / 128), 256>>>(
            MTOT, EMBED, MLPD, mlp, fc2_w + (size_t)L * MLPD * EMBED, dst,
            fc2_b + L * EMBED, h);
    }
}